// round 14
// baseline (speedup 1.0000x reference)
#include <cuda_runtime.h>
#include <cuda_fp16.h>
#include <cstdint>

// GRU encoder via mma.sync (HMMA fp16, f32 accum). 16 warps/CTA, 148 CTAs x 80 seqs.
// Gate-selective precision: r,z = fp16 hi-only; n = hi+lo. log2(e) folded into
// weights (exp == bare ex2.approx). fc feedback u = fcw.h via mini-MMA FUSED into
// the main K-loop (warps 0..4, m-tile w), published via smem. pvv prefetched
// above the barrier. A double-buffered. Exact fp32 h state in smem.

#define TT 24
#define NNN 184
#define SEQ 11776
#define M_CTA 80
#define GRIDX 148
#define NT 512
#define H_ELEMS 36175872ULL
#define HSTRIDE 132
#define L2E 1.4426950408889634f

// smem byte offsets
#define SM_WHI    0                 /* 392*256 = 100352 (rows 384..391 = fcw) */
#define SM_A0     100352            /* 80*256 = 20480 */
#define SM_A1     120832            /* 80*256 = 20480 */
#define SM_HST    141312            /* 80*132*4 = 42240 */
#define SM_W0     183552
#define SM_W1     185088
#define SM_BS     186624
#define SM_FCW    188672
#define SM_CSROW  189184
#define SM_US     189504            /* 80 floats */
#define SM_XPART  189824            /* 16*80*4 = 5120 */
#define SMEM_BYTES 194944

__device__ __align__(16) uint32_t g_wlofrag[16 * 32 * 16];  // 32KB (n-gate only)

__device__ __forceinline__ uint32_t smem_u32(const void* p) {
    uint32_t a;
    asm("{ .reg .u64 t; cvta.to.shared.u64 t, %1; cvt.u32.u64 %0, t; }" : "=r"(a) : "l"(p));
    return a;
}

#define LDSM4(r0, r1, r2, r3, addr) \
    asm volatile("ldmatrix.sync.aligned.m8n8.x4.shared.b16 {%0,%1,%2,%3}, [%4];" \
        : "=r"(r0), "=r"(r1), "=r"(r2), "=r"(r3) : "r"(addr))
#define LDSM2(r0, r1, addr) \
    asm volatile("ldmatrix.sync.aligned.m8n8.x2.shared.b16 {%0,%1}, [%2];" \
        : "=r"(r0), "=r"(r1) : "r"(addr))

#define MMA16816(c, a, b) \
    asm volatile("mma.sync.aligned.m16n8k16.row.col.f32.f16.f16.f32 " \
        "{%0,%1,%2,%3}, {%4,%5,%6,%7}, {%8,%9}, {%0,%1,%2,%3};" \
        : "+f"((c)[0]), "+f"((c)[1]), "+f"((c)[2]), "+f"((c)[3]) \
        : "r"((a)[0]), "r"((a)[1]), "r"((a)[2]), "r"((a)[3]), \
          "r"((b)[0]), "r"((b)[1]))

__device__ __forceinline__ uint32_t packh2(float x, float y) {
    __half2 h = __floats2half2_rn(x, y);
    return *(uint32_t*)&h;
}
__device__ __forceinline__ float frcp(float x) {
    float y;
    asm("rcp.approx.f32 %0, %1;" : "=f"(y) : "f"(x));
    return y;
}
__device__ __forceinline__ float fex2(float x) {
    float y;
    asm("ex2.approx.f32 %0, %1;" : "=f"(y) : "f"(x));
    return y;
}

// ---- setup: pack n-gate Wlo = S*W - fp16(S*W), S = 2*log2(e) ----
__global__ void pack_wlo_kernel(const float* __restrict__ Whh) {
    int t = blockIdx.x * blockDim.x + threadIdx.x;
    if (t >= 4096) return;
    int K = t & 7, l = (t >> 3) & 31, w = t >> 8;
    const float S = 2.f * L2E;
#pragma unroll
    for (int r = 0; r < 2; r++) {
        int j = 8 * (w + 32) + (l >> 2);
        int k0 = 16 * K + 8 * r + 2 * (l & 3);
        float w0 = S * Whh[j * 128 + k0], w1 = S * Whh[j * 128 + k0 + 1];
        float l0 = w0 - __half2float(__float2half_rn(w0));
        float l1 = w1 - __half2float(__float2half_rn(w1));
        g_wlofrag[(w * 32 + l) * 16 + K * 2 + r] = packh2(l0, l1);
    }
}

__global__ void __launch_bounds__(NT, 1)
gru_mma_kernel(const float* __restrict__ pm,
               const float* __restrict__ Wih,
               const float* __restrict__ Whh,
               const float* __restrict__ bih_g,
               const float* __restrict__ bhh_g,
               const float* __restrict__ fcw_g,
               const float* __restrict__ fcb_g,
               float* __restrict__ out)
{
    extern __shared__ char smem[];
    const uint32_t smb = smem_u32(smem);
    const int tid = threadIdx.x;
    const int lane = tid & 31;
    const int w = tid >> 5;
    const int bid80 = blockIdx.x * M_CTA;

    float* w0s   = (float*)(smem + SM_W0);
    float* w1s   = (float*)(smem + SM_W1);
    float* bss   = (float*)(smem + SM_BS);
    float* fcws  = (float*)(smem + SM_FCW);
    int*   csrow = (int*)  (smem + SM_CSROW);
    float* us    = (float*)(smem + SM_US);
    float* xpart = (float*)(smem + SM_XPART);
    float* hst   = (float*)(smem + SM_HST);

    const float fcb = fcb_g[0];

    // stage Whi = fp16(scale*Whh) swizzled; scale = L2E (r,z) / 2*L2E (n)
    {
        const float4* Wg = (const float4*)Whh;
        for (int v = tid; v < 384 * 32; v += NT) {
            int j = v >> 5, k4 = (v & 31) * 4;
            float sc = (j < 256) ? L2E : (2.f * L2E);
            float4 wv = Wg[v];
            uint32_t off = (uint32_t)(j * 256 + ((((k4 >> 3) ^ (j & 7))) << 4) + (k4 & 7) * 2);
            *(uint2*)(smem + SM_WHI + off) =
                make_uint2(packh2(sc * wv.x, sc * wv.y), packh2(sc * wv.z, sc * wv.w));
        }
    }
    // W rows 384..391 = fcw (fp16, UNscaled), replicated
    for (int v = tid; v < 8 * 32; v += NT) {
        int j = 384 + (v >> 5), k4 = (v & 31) * 4;
        float f0 = fcw_g[k4], f1 = fcw_g[k4 + 1], f2 = fcw_g[k4 + 2], f3 = fcw_g[k4 + 3];
        uint32_t off = (uint32_t)(j * 256 + ((((k4 >> 3) ^ (j & 7))) << 4) + (k4 & 7) * 2);
        *(uint2*)(smem + SM_WHI + off) = make_uint2(packh2(f0, f1), packh2(f2, f3));
    }
    // zero both A buffers and Hst
    for (int v = tid; v < 40960 / 8; v += NT)
        ((uint2*)(smem + SM_A0))[v] = make_uint2(0u, 0u);
    for (int v = tid; v < 80 * HSTRIDE; v += NT)
        hst[v] = 0.f;

    for (int i = tid; i < 384; i += NT) {
        float sc = (i < 256) ? L2E : (2.f * L2E);
        w0s[i] = sc * Wih[2 * i];
        w1s[i] = sc * Wih[2 * i + 1];
    }
    if (tid < 128) {
        bss[tid]       = L2E * (bih_g[tid]       + bhh_g[tid]);
        bss[128 + tid] = L2E * (bih_g[128 + tid] + bhh_g[128 + tid]);
        bss[256 + tid] = 2.f * L2E * bih_g[256 + tid];
        bss[384 + tid] = 2.f * L2E * bhh_g[256 + tid];
        fcws[tid] = fcw_g[tid];
    }
    if (tid < M_CTA) {
        int s = bid80 + tid;
        bool v = s < SEQ;
        int ss = v ? s : 0;
        int b = ss / NNN, n = ss % NNN;
        csrow[tid] = b * TT * NNN + n;
    }
    __syncthreads();

    // lane roles
    const uint32_t lx7 = lane & 7;
    const uint32_t rA  = (lane & 7) + ((lane >> 3) & 1) * 8;
    const uint32_t cA  = lane >> 4;
    const uint32_t cB  = (lane >> 3) & 1;
    const int q = lane >> 2, p4 = lane & 3;

    const uint32_t wA4 = smb + SM_WHI
        + (uint32_t)((8 * w + (lane & 7) + (((lane >> 4) & 1) << 7)) * 256);
    const uint32_t wA2 = smb + SM_WHI
        + (uint32_t)((8 * w + 256 + (lane & 7)) * 256);
    const uint32_t wA48 = smb + SM_WHI + (uint32_t)((384 + (lane & 7)) * 256);
    uint32_t rowOff[5];
#pragma unroll
    for (int mt = 0; mt < 5; mt++)
        rowOff[mt] = (uint32_t)((16 * mt + rA) * 256);

    const uint2* wloN = (const uint2*)(g_wlofrag) + (size_t)((w * 32 + lane) * 8);
    const int c0 = 8 * w + 2 * p4;
    const bool miniW = (w < 5);

    float w0r[2], w1r[2], br[2], w0z[2], w1z[2], bz[2],
          w0n[2], w1n[2], bi_n[2], bh_n[2], fc[2];
#pragma unroll
    for (int e = 0; e < 2; e++) {
        const int c = c0 + e;
        w0r[e] = w0s[c];       w1r[e] = w1s[c];       br[e] = bss[c];
        w0z[e] = w0s[128 + c]; w1z[e] = w1s[128 + c]; bz[e] = bss[128 + c];
        w0n[e] = w0s[256 + c]; w1n[e] = w1s[256 + c];
        bi_n[e] = bss[256 + c]; bh_n[e] = bss[384 + c];
        fc[e] = fcws[c];
    }

    for (int t = 0; t < TT; t++) {
        const uint32_t aRd = smb + ((t & 1) ? SM_A1 : SM_A0);
        const uint32_t aWrOff = (t & 1) ? SM_A0 : SM_A1;

        float acc[3][5][4];
#pragma unroll
        for (int g = 0; g < 3; g++)
#pragma unroll
            for (int mt = 0; mt < 5; mt++)
#pragma unroll
                for (int e = 0; e < 4; e++) acc[g][mt][e] = 0.f;
        float acc48[4] = {0.f, 0.f, 0.f, 0.f};

        // main MMA: r,z hi-only; n hi+lo; fused mini-MMA (warp w<5, m-tile w)
        {
            uint2 pf = __ldg(wloN);
#pragma unroll
            for (int K = 0; K < 8; K++) {
                uint32_t bl[2];
                bl[0] = pf.x; bl[1] = pf.y;
                if (K < 7) pf = __ldg(wloN + K + 1);
                const uint32_t offA = ((2u * K + cA) ^ lx7) << 4;
                uint32_t a[5][4];
#pragma unroll
                for (int mt = 0; mt < 5; mt++)
                    LDSM4(a[mt][0], a[mt][1], a[mt][2], a[mt][3],
                          aRd + rowOff[mt] + offA);
                const uint32_t offW = ((2u * K + cB) ^ lx7) << 4;
                uint32_t bh[3][2];
                LDSM4(bh[0][0], bh[0][1], bh[1][0], bh[1][1], wA4 + offW);
                LDSM2(bh[2][0], bh[2][1], wA2 + offW);
#pragma unroll
                for (int mt = 0; mt < 5; mt++) {
                    MMA16816(acc[0][mt], a[mt], bh[0]);
                    MMA16816(acc[1][mt], a[mt], bh[1]);
                    MMA16816(acc[2][mt], a[mt], bh[2]);
                    MMA16816(acc[2][mt], a[mt], bl);
                }
                if (miniW) {   // fused u-GEMM: reuse a[w], one LDSM2 + one MMA
                    uint32_t b48[2];
                    LDSM2(b48[0], b48[1], wA48 + offW);
                    MMA16816(acc48, a[w], b48);
                }
            }
        }
        if (miniW && p4 == 0) {
            us[16 * w + q]     = acc48[0];
            us[16 * w + 8 + q] = acc48[2];
        }

        // prefetch pm for this step BEFORE the barrier (hides L2 latency)
        float pvv[10];
#pragma unroll
        for (int mt = 0; mt < 5; mt++)
#pragma unroll
            for (int hf = 0; hf < 2; hf++)
                pvv[mt * 2 + hf] = __ldg(pm + csrow[16 * mt + 8 * hf + q] + t * NNN);

        __syncthreads();   // publish us[]; all A reads complete

        // ---- epilogue ----
        float* outT = out + (size_t)t * (NNN * 128);
        float hnv[10][2];

#pragma unroll
        for (int mt = 0; mt < 5; mt++)
#pragma unroll
            for (int hf = 0; hf < 2; hf++) {
                const int row = 16 * mt + 8 * hf + q;
                const float xm = (t == 0) ? 0.f : (us[row] + fcb);
                const float pv = pvv[mt * 2 + hf];
                float2 ho2 = *(float2*)(hst + row * HSTRIDE + c0);
                const int r0i = hf * 2, r1i = hf * 2 + 1;

                const float gr0 = acc[0][mt][r0i] + fmaf(w0r[0], xm, fmaf(w1r[0], pv, br[0]));
                const float gr1 = acc[0][mt][r1i] + fmaf(w0r[1], xm, fmaf(w1r[1], pv, br[1]));
                const float gz0 = acc[1][mt][r0i] + fmaf(w0z[0], xm, fmaf(w1z[0], pv, bz[0]));
                const float gz1 = acc[1][mt][r1i] + fmaf(w0z[1], xm, fmaf(w1z[1], pv, bz[1]));
                const float dr0 = 1.f + fex2(-gr0);
                const float dr1 = 1.f + fex2(-gr1);
                const float dz0 = 1.f + fex2(-gz0);
                const float dz1 = 1.f + fex2(-gz1);
                const float m0 = dr0 * dr1, m1 = dz0 * dz1;
                const float rp = frcp(m0 * m1);
                const float r_0 = (dr1 * m1) * rp;
                const float r_1 = (dr0 * m1) * rp;
                const float z_0 = (m0 * dz1) * rp;
                const float z_1 = (m0 * dz0) * rp;

                const float a0 = fmaf(w0n[0], xm, fmaf(w1n[0], pv, bi_n[0]))
                               + r_0 * (acc[2][mt][r0i] + bh_n[0]);
                const float a1 = fmaf(w0n[1], xm, fmaf(w1n[1], pv, bi_n[1]))
                               + r_1 * (acc[2][mt][r1i] + bh_n[1]);
                const float dn0 = 1.f + fex2(a0);
                const float dn1 = 1.f + fex2(a1);
                const float rq = frcp(dn0 * dn1);
                const float nt0 = fmaf(-2.f, dn1 * rq, 1.f);
                const float nt1 = fmaf(-2.f, dn0 * rq, 1.f);

                const float hn0 = nt0 + z_0 * (ho2.x - nt0);
                const float hn1 = nt1 + z_1 * (ho2.y - nt1);
                hnv[mt * 2 + hf][0] = hn0;
                hnv[mt * 2 + hf][1] = hn1;

                *(float2*)(hst + row * HSTRIDE + c0) = make_float2(hn0, hn1);
                if (bid80 + row < SEQ)
                    *(float2*)(outT + (size_t)csrow[row] * 128 + c0)
                        = make_float2(hn0, hn1);
                const uint32_t aoff = (uint32_t)(row * 256 + ((w ^ q) << 4) + 4 * p4);
                *(uint32_t*)(smem + aWrOff + aoff) = packh2(hn0, hn1);
            }

        if (t == TT - 1) {   // exact fp32 final-x partials (once)
#pragma unroll
            for (int i = 0; i < 10; i++) {
                float v = fmaf(hnv[i][0], fc[0], hnv[i][1] * fc[1]);
                v += __shfl_xor_sync(0xFFFFFFFFu, v, 1);
                v += __shfl_xor_sync(0xFFFFFFFFu, v, 2);
                if (p4 == 0) {
                    const int row = 16 * (i >> 1) + 8 * (i & 1) + q;
                    xpart[w * 80 + row] = v;
                }
            }
        }
        __syncthreads();   // A writes + (last step) xpart visible
    }

    // final xn output (exact fp32)
    if (tid < M_CTA) {
        float sx = fcb;
#pragma unroll
        for (int ww = 0; ww < 16; ww++) sx += xpart[ww * 80 + tid];
        if (bid80 + tid < SEQ)
            out[H_ELEMS + (size_t)(bid80 + tid)] = sx;
    }
}

extern "C" void kernel_launch(void* const* d_in, const int* in_sizes, int n_in,
                              void* d_out, int out_size) {
    (void)in_sizes; (void)n_in; (void)out_size;
    const float* pm  = (const float*)d_in[0];
    const float* Wih = (const float*)d_in[1];
    const float* Whh = (const float*)d_in[2];
    const float* bih = (const float*)d_in[3];
    const float* bhh = (const float*)d_in[4];
    const float* fcw = (const float*)d_in[5];
    const float* fcb = (const float*)d_in[6];
    float* out = (float*)d_out;

    pack_wlo_kernel<<<16, 256>>>(Whh);
    cudaFuncSetAttribute(gru_mma_kernel,
                         cudaFuncAttributeMaxDynamicSharedMemorySize,
                         SMEM_BYTES);
    gru_mma_kernel<<<GRIDX, NT, SMEM_BYTES>>>(
        pm, Wih, Whh, bih, bhh, fcw, fcb, out);
}

// round 15
// speedup vs baseline: 1.4382x; 1.4382x over previous
#include <cuda_runtime.h>
#include <cuda_fp16.h>
#include <cstdint>

// GRU encoder via mma.sync (HMMA fp16, f32 accum). 16 warps/CTA, 148 CTAs x 80 seqs.
// Gate-selective precision: r,z = fp16 hi-only; n = hi+lo 2-pass. log2(e) folded
// into weights (exp == bare ex2.approx). fc feedback u = fcw.h via DISTRIBUTED
// mini-MMA split over 10 warps by K-halves (partials summed in epilogue).
// A double-buffered. Exact fp32 h state in smem. (R13 shape — no added liveness.)

#define TT 24
#define NNN 184
#define SEQ 11776
#define M_CTA 80
#define GRIDX 148
#define NT 512
#define H_ELEMS 36175872ULL
#define HSTRIDE 132
#define L2E 1.4426950408889634f

// smem byte offsets
#define SM_WHI    0                 /* 392*256 = 100352 (rows 384..391 = fcw) */
#define SM_A0     100352            /* 80*256 = 20480 */
#define SM_A1     120832            /* 80*256 = 20480 */
#define SM_HST    141312            /* 80*132*4 = 42240 */
#define SM_W0     183552
#define SM_W1     185088
#define SM_BS     186624
#define SM_FCW    188672
#define SM_CSROW  189184
#define SM_US     189504            /* 2*80 floats = 640B */
#define SM_XPART  190144            /* 16*80*4 = 5120 */
#define SMEM_BYTES 195264

__device__ __align__(16) uint32_t g_wlofrag[16 * 32 * 16];  // 32KB (n-gate only)

__device__ __forceinline__ uint32_t smem_u32(const void* p) {
    uint32_t a;
    asm("{ .reg .u64 t; cvta.to.shared.u64 t, %1; cvt.u32.u64 %0, t; }" : "=r"(a) : "l"(p));
    return a;
}

#define LDSM4(r0, r1, r2, r3, addr) \
    asm volatile("ldmatrix.sync.aligned.m8n8.x4.shared.b16 {%0,%1,%2,%3}, [%4];" \
        : "=r"(r0), "=r"(r1), "=r"(r2), "=r"(r3) : "r"(addr))
#define LDSM2(r0, r1, addr) \
    asm volatile("ldmatrix.sync.aligned.m8n8.x2.shared.b16 {%0,%1}, [%2];" \
        : "=r"(r0), "=r"(r1) : "r"(addr))

#define MMA16816(c, a, b) \
    asm volatile("mma.sync.aligned.m16n8k16.row.col.f32.f16.f16.f32 " \
        "{%0,%1,%2,%3}, {%4,%5,%6,%7}, {%8,%9}, {%0,%1,%2,%3};" \
        : "+f"((c)[0]), "+f"((c)[1]), "+f"((c)[2]), "+f"((c)[3]) \
        : "r"((a)[0]), "r"((a)[1]), "r"((a)[2]), "r"((a)[3]), \
          "r"((b)[0]), "r"((b)[1]))

__device__ __forceinline__ uint32_t packh2(float x, float y) {
    __half2 h = __floats2half2_rn(x, y);
    return *(uint32_t*)&h;
}
__device__ __forceinline__ float frcp(float x) {
    float y;
    asm("rcp.approx.f32 %0, %1;" : "=f"(y) : "f"(x));
    return y;
}
__device__ __forceinline__ float fex2(float x) {
    float y;
    asm("ex2.approx.f32 %0, %1;" : "=f"(y) : "f"(x));
    return y;
}

// ---- setup: pack n-gate Wlo = S*W - fp16(S*W), S = 2*log2(e) ----
__global__ void pack_wlo_kernel(const float* __restrict__ Whh) {
    int t = blockIdx.x * blockDim.x + threadIdx.x;
    if (t >= 4096) return;
    int K = t & 7, l = (t >> 3) & 31, w = t >> 8;
    const float S = 2.f * L2E;
#pragma unroll
    for (int r = 0; r < 2; r++) {
        int j = 8 * (w + 32) + (l >> 2);
        int k0 = 16 * K + 8 * r + 2 * (l & 3);
        float w0 = S * Whh[j * 128 + k0], w1 = S * Whh[j * 128 + k0 + 1];
        float l0 = w0 - __half2float(__float2half_rn(w0));
        float l1 = w1 - __half2float(__float2half_rn(w1));
        g_wlofrag[(w * 32 + l) * 16 + K * 2 + r] = packh2(l0, l1);
    }
}

__global__ void __launch_bounds__(NT, 1)
gru_mma_kernel(const float* __restrict__ pm,
               const float* __restrict__ Wih,
               const float* __restrict__ Whh,
               const float* __restrict__ bih_g,
               const float* __restrict__ bhh_g,
               const float* __restrict__ fcw_g,
               const float* __restrict__ fcb_g,
               float* __restrict__ out)
{
    extern __shared__ char smem[];
    const uint32_t smb = smem_u32(smem);
    const int tid = threadIdx.x;
    const int lane = tid & 31;
    const int w = tid >> 5;
    const int bid80 = blockIdx.x * M_CTA;

    float* w0s   = (float*)(smem + SM_W0);
    float* w1s   = (float*)(smem + SM_W1);
    float* bss   = (float*)(smem + SM_BS);
    float* fcws  = (float*)(smem + SM_FCW);
    int*   csrow = (int*)  (smem + SM_CSROW);
    float* us    = (float*)(smem + SM_US);     // us[0..79], us[80..159]
    float* xpart = (float*)(smem + SM_XPART);
    float* hst   = (float*)(smem + SM_HST);

    const float fcb = fcb_g[0];

    // stage Whi = fp16(scale*Whh) swizzled; scale = L2E (r,z) / 2*L2E (n)
    {
        const float4* Wg = (const float4*)Whh;
        for (int v = tid; v < 384 * 32; v += NT) {
            int j = v >> 5, k4 = (v & 31) * 4;
            float sc = (j < 256) ? L2E : (2.f * L2E);
            float4 wv = Wg[v];
            uint32_t off = (uint32_t)(j * 256 + ((((k4 >> 3) ^ (j & 7))) << 4) + (k4 & 7) * 2);
            *(uint2*)(smem + SM_WHI + off) =
                make_uint2(packh2(sc * wv.x, sc * wv.y), packh2(sc * wv.z, sc * wv.w));
        }
    }
    // W rows 384..391 = fcw (fp16, UNscaled), replicated
    for (int v = tid; v < 8 * 32; v += NT) {
        int j = 384 + (v >> 5), k4 = (v & 31) * 4;
        float f0 = fcw_g[k4], f1 = fcw_g[k4 + 1], f2 = fcw_g[k4 + 2], f3 = fcw_g[k4 + 3];
        uint32_t off = (uint32_t)(j * 256 + ((((k4 >> 3) ^ (j & 7))) << 4) + (k4 & 7) * 2);
        *(uint2*)(smem + SM_WHI + off) = make_uint2(packh2(f0, f1), packh2(f2, f3));
    }
    // zero both A buffers and Hst
    for (int v = tid; v < 40960 / 8; v += NT)
        ((uint2*)(smem + SM_A0))[v] = make_uint2(0u, 0u);
    for (int v = tid; v < 80 * HSTRIDE; v += NT)
        hst[v] = 0.f;

    for (int i = tid; i < 384; i += NT) {
        float sc = (i < 256) ? L2E : (2.f * L2E);
        w0s[i] = sc * Wih[2 * i];
        w1s[i] = sc * Wih[2 * i + 1];
    }
    if (tid < 128) {
        bss[tid]       = L2E * (bih_g[tid]       + bhh_g[tid]);
        bss[128 + tid] = L2E * (bih_g[128 + tid] + bhh_g[128 + tid]);
        bss[256 + tid] = 2.f * L2E * bih_g[256 + tid];
        bss[384 + tid] = 2.f * L2E * bhh_g[256 + tid];
        fcws[tid] = fcw_g[tid];
    }
    if (tid < M_CTA) {
        int s = bid80 + tid;
        bool v = s < SEQ;
        int ss = v ? s : 0;
        int b = ss / NNN, n = ss % NNN;
        csrow[tid] = b * TT * NNN + n;
    }
    __syncthreads();

    // lane roles
    const uint32_t lx7 = lane & 7;
    const uint32_t rA  = (lane & 7) + ((lane >> 3) & 1) * 8;
    const uint32_t cA  = lane >> 4;
    const uint32_t cB  = (lane >> 3) & 1;
    const int q = lane >> 2, p4 = lane & 3;

    const uint32_t wA4 = smb + SM_WHI
        + (uint32_t)((8 * w + (lane & 7) + (((lane >> 4) & 1) << 7)) * 256);
    const uint32_t wA2 = smb + SM_WHI
        + (uint32_t)((8 * w + 256 + (lane & 7)) * 256);
    const uint32_t wA48 = smb + SM_WHI + (uint32_t)((384 + (lane & 7)) * 256);
    uint32_t rowOff[5];
#pragma unroll
    for (int mt = 0; mt < 5; mt++)
        rowOff[mt] = (uint32_t)((16 * mt + rA) * 256);

    const uint2* wloN = (const uint2*)(g_wlofrag) + (size_t)((w * 32 + lane) * 8);
    const int c0 = 8 * w + 2 * p4;
    // mini-MMA assignment: warps 0..9, m-tile = w>>1, K-half = w&1
    const int miniMT = w >> 1;
    const int miniK0 = (w & 1) * 4;

    float w0r[2], w1r[2], br[2], w0z[2], w1z[2], bz[2],
          w0n[2], w1n[2], bi_n[2], bh_n[2], fc[2];
#pragma unroll
    for (int e = 0; e < 2; e++) {
        const int c = c0 + e;
        w0r[e] = w0s[c];       w1r[e] = w1s[c];       br[e] = bss[c];
        w0z[e] = w0s[128 + c]; w1z[e] = w1s[128 + c]; bz[e] = bss[128 + c];
        w0n[e] = w0s[256 + c]; w1n[e] = w1s[256 + c];
        bi_n[e] = bss[256 + c]; bh_n[e] = bss[384 + c];
        fc[e] = fcws[c];
    }

    for (int t = 0; t < TT; t++) {
        const uint32_t aRd = smb + ((t & 1) ? SM_A1 : SM_A0);
        const uint32_t aWrOff = (t & 1) ? SM_A0 : SM_A1;

        float acc[3][5][4];
#pragma unroll
        for (int g = 0; g < 3; g++)
#pragma unroll
            for (int mt = 0; mt < 5; mt++)
#pragma unroll
                for (int e = 0; e < 4; e++) acc[g][mt][e] = 0.f;

        // main MMA: r,z hi-only; n hi+lo (n-lo prefetched distance-1)
        {
            uint2 pf = __ldg(wloN);
#pragma unroll
            for (int K = 0; K < 8; K++) {
                uint32_t bl[2];
                bl[0] = pf.x; bl[1] = pf.y;
                if (K < 7) pf = __ldg(wloN + K + 1);
                const uint32_t offA = ((2u * K + cA) ^ lx7) << 4;
                uint32_t a[5][4];
#pragma unroll
                for (int mt = 0; mt < 5; mt++)
                    LDSM4(a[mt][0], a[mt][1], a[mt][2], a[mt][3],
                          aRd + rowOff[mt] + offA);
                const uint32_t offW = ((2u * K + cB) ^ lx7) << 4;
                uint32_t bh[3][2];
                LDSM4(bh[0][0], bh[0][1], bh[1][0], bh[1][1], wA4 + offW);
                LDSM2(bh[2][0], bh[2][1], wA2 + offW);
#pragma unroll
                for (int mt = 0; mt < 5; mt++) {
                    MMA16816(acc[0][mt], a[mt], bh[0]);
                    MMA16816(acc[1][mt], a[mt], bh[1]);
                    MMA16816(acc[2][mt], a[mt], bh[2]);
                    MMA16816(acc[2][mt], a[mt], bl);
                }
            }
        }

        // distributed mini MMA: 10 warps, K-half split (4 K-iters each)
        if (w < 10) {
            float acc48[4] = {0.f, 0.f, 0.f, 0.f};
#pragma unroll
            for (int Ki = 0; Ki < 4; Ki++) {
                const int K = miniK0 + Ki;
                const uint32_t offA = ((2u * K + cA) ^ lx7) << 4;
                const uint32_t offW = ((2u * K + cB) ^ lx7) << 4;
                uint32_t b48[2];
                LDSM2(b48[0], b48[1], wA48 + offW);
                uint32_t a[4];
                LDSM4(a[0], a[1], a[2], a[3], aRd + rowOff[miniMT] + offA);
                MMA16816(acc48, a, b48);
            }
            if (p4 == 0) {
                us[(w & 1) * 80 + 16 * miniMT + q]     = acc48[0];
                us[(w & 1) * 80 + 16 * miniMT + 8 + q] = acc48[2];
            }
        }
        __syncthreads();   // publish us[]; all A reads complete

        // ---- epilogue ----
        float pvv[10];
#pragma unroll
        for (int mt = 0; mt < 5; mt++)
#pragma unroll
            for (int hf = 0; hf < 2; hf++)
                pvv[mt * 2 + hf] = __ldg(pm + csrow[16 * mt + 8 * hf + q] + t * NNN);

        float* outT = out + (size_t)t * (NNN * 128);

#pragma unroll
        for (int mt = 0; mt < 5; mt++)
#pragma unroll
            for (int hf = 0; hf < 2; hf++) {
                const int row = 16 * mt + 8 * hf + q;
                const float xm = (t == 0) ? 0.f : (us[row] + us[80 + row] + fcb);
                const float pv = pvv[mt * 2 + hf];
                float2 ho2 = *(float2*)(hst + row * HSTRIDE + c0);
                const int r0i = hf * 2, r1i = hf * 2 + 1;

                const float gr0 = acc[0][mt][r0i] + fmaf(w0r[0], xm, fmaf(w1r[0], pv, br[0]));
                const float gr1 = acc[0][mt][r1i] + fmaf(w0r[1], xm, fmaf(w1r[1], pv, br[1]));
                const float gz0 = acc[1][mt][r0i] + fmaf(w0z[0], xm, fmaf(w1z[0], pv, bz[0]));
                const float gz1 = acc[1][mt][r1i] + fmaf(w0z[1], xm, fmaf(w1z[1], pv, bz[1]));
                const float dr0 = 1.f + fex2(-gr0);
                const float dr1 = 1.f + fex2(-gr1);
                const float dz0 = 1.f + fex2(-gz0);
                const float dz1 = 1.f + fex2(-gz1);
                const float m0 = dr0 * dr1, m1 = dz0 * dz1;
                const float rp = frcp(m0 * m1);
                const float r_0 = (dr1 * m1) * rp;
                const float r_1 = (dr0 * m1) * rp;
                const float z_0 = (m0 * dz1) * rp;
                const float z_1 = (m0 * dz0) * rp;

                const float a0 = fmaf(w0n[0], xm, fmaf(w1n[0], pv, bi_n[0]))
                               + r_0 * (acc[2][mt][r0i] + bh_n[0]);
                const float a1 = fmaf(w0n[1], xm, fmaf(w1n[1], pv, bi_n[1]))
                               + r_1 * (acc[2][mt][r1i] + bh_n[1]);
                const float dn0 = 1.f + fex2(a0);
                const float dn1 = 1.f + fex2(a1);
                const float rq = frcp(dn0 * dn1);
                const float nt0 = fmaf(-2.f, dn1 * rq, 1.f);
                const float nt1 = fmaf(-2.f, dn0 * rq, 1.f);

                const float hn0 = nt0 + z_0 * (ho2.x - nt0);
                const float hn1 = nt1 + z_1 * (ho2.y - nt1);

                *(float2*)(hst + row * HSTRIDE + c0) = make_float2(hn0, hn1);
                if (bid80 + row < SEQ)
                    *(float2*)(outT + (size_t)csrow[row] * 128 + c0)
                        = make_float2(hn0, hn1);
                const uint32_t aoff = (uint32_t)(row * 256 + ((w ^ q) << 4) + 4 * p4);
                *(uint32_t*)(smem + aWrOff + aoff) = packh2(hn0, hn1);

                if (t == TT - 1) {   // exact fp32 final-x partials (last step only)
                    float v = fmaf(hn0, fc[0], hn1 * fc[1]);
                    v += __shfl_xor_sync(0xFFFFFFFFu, v, 1);
                    v += __shfl_xor_sync(0xFFFFFFFFu, v, 2);
                    if (p4 == 0) xpart[w * 80 + row] = v;
                }
            }
        __syncthreads();   // A writes + (last step) xpart visible
    }

    // final xn output (exact fp32)
    if (tid < M_CTA) {
        float sx = fcb;
#pragma unroll
        for (int ww = 0; ww < 16; ww++) sx += xpart[ww * 80 + tid];
        if (bid80 + tid < SEQ)
            out[H_ELEMS + (size_t)(bid80 + tid)] = sx;
    }
}

extern "C" void kernel_launch(void* const* d_in, const int* in_sizes, int n_in,
                              void* d_out, int out_size) {
    (void)in_sizes; (void)n_in; (void)out_size;
    const float* pm  = (const float*)d_in[0];
    const float* Wih = (const float*)d_in[1];
    const float* Whh = (const float*)d_in[2];
    const float* bih = (const float*)d_in[3];
    const float* bhh = (const float*)d_in[4];
    const float* fcw = (const float*)d_in[5];
    const float* fcb = (const float*)d_in[6];
    float* out = (float*)d_out;

    pack_wlo_kernel<<<16, 256>>>(Whh);
    cudaFuncSetAttribute(gru_mma_kernel,
                         cudaFuncAttributeMaxDynamicSharedMemorySize,
                         SMEM_BYTES);
    gru_mma_kernel<<<GRIDX, NT, SMEM_BYTES>>>(
        pm, Wih, Whh, bih, bhh, fcw, fcb, out);
}

// round 16
// speedup vs baseline: 1.7756x; 1.2346x over previous
#include <cuda_runtime.h>
#include <cuda_fp16.h>
#include <cstdint>

// GRU encoder via mma.sync (HMMA fp16, f32 accum). 16 warps/CTA, 148 CTAs x 80 seqs.
// All gates fp16 hi-only MMA (measured: W-rounding error is dominated by the fp16
// h quantization; see R8 vs R12 rel_err). log2(e) folded into weights (exp ==
// bare ex2.approx). fc feedback u = fcw.h via distributed mini-MMA (10 warps,
// K-halves). pm prefetched above the barrier. A double-buffered, 2 barriers/step.
// Exact fp32 h state in smem.

#define TT 24
#define NNN 184
#define SEQ 11776
#define M_CTA 80
#define GRIDX 148
#define NT 512
#define H_ELEMS 36175872ULL
#define HSTRIDE 132
#define L2E 1.4426950408889634f

// smem byte offsets
#define SM_WHI    0                 /* 392*256 = 100352 (rows 384..391 = fcw) */
#define SM_A0     100352            /* 80*256 = 20480 */
#define SM_A1     120832            /* 80*256 = 20480 */
#define SM_HST    141312            /* 80*132*4 = 42240 */
#define SM_W0     183552
#define SM_W1     185088
#define SM_BS     186624
#define SM_FCW    188672
#define SM_CSROW  189184
#define SM_US     189504            /* 2*80 floats = 640B */
#define SM_XPART  190144            /* 16*80*4 = 5120 */
#define SMEM_BYTES 195264

__device__ __forceinline__ uint32_t smem_u32(const void* p) {
    uint32_t a;
    asm("{ .reg .u64 t; cvta.to.shared.u64 t, %1; cvt.u32.u64 %0, t; }" : "=r"(a) : "l"(p));
    return a;
}

#define LDSM4(r0, r1, r2, r3, addr) \
    asm volatile("ldmatrix.sync.aligned.m8n8.x4.shared.b16 {%0,%1,%2,%3}, [%4];" \
        : "=r"(r0), "=r"(r1), "=r"(r2), "=r"(r3) : "r"(addr))
#define LDSM2(r0, r1, addr) \
    asm volatile("ldmatrix.sync.aligned.m8n8.x2.shared.b16 {%0,%1}, [%2];" \
        : "=r"(r0), "=r"(r1) : "r"(addr))

#define MMA16816(c, a, b) \
    asm volatile("mma.sync.aligned.m16n8k16.row.col.f32.f16.f16.f32 " \
        "{%0,%1,%2,%3}, {%4,%5,%6,%7}, {%8,%9}, {%0,%1,%2,%3};" \
        : "+f"((c)[0]), "+f"((c)[1]), "+f"((c)[2]), "+f"((c)[3]) \
        : "r"((a)[0]), "r"((a)[1]), "r"((a)[2]), "r"((a)[3]), \
          "r"((b)[0]), "r"((b)[1]))

__device__ __forceinline__ uint32_t packh2(float x, float y) {
    __half2 h = __floats2half2_rn(x, y);
    return *(uint32_t*)&h;
}
__device__ __forceinline__ float frcp(float x) {
    float y;
    asm("rcp.approx.f32 %0, %1;" : "=f"(y) : "f"(x));
    return y;
}
__device__ __forceinline__ float fex2(float x) {
    float y;
    asm("ex2.approx.f32 %0, %1;" : "=f"(y) : "f"(x));
    return y;
}

__global__ void __launch_bounds__(NT, 1)
gru_mma_kernel(const float* __restrict__ pm,
               const float* __restrict__ Wih,
               const float* __restrict__ Whh,
               const float* __restrict__ bih_g,
               const float* __restrict__ bhh_g,
               const float* __restrict__ fcw_g,
               const float* __restrict__ fcb_g,
               float* __restrict__ out)
{
    extern __shared__ char smem[];
    const uint32_t smb = smem_u32(smem);
    const int tid = threadIdx.x;
    const int lane = tid & 31;
    const int w = tid >> 5;
    const int bid80 = blockIdx.x * M_CTA;

    float* w0s   = (float*)(smem + SM_W0);
    float* w1s   = (float*)(smem + SM_W1);
    float* bss   = (float*)(smem + SM_BS);
    float* fcws  = (float*)(smem + SM_FCW);
    int*   csrow = (int*)  (smem + SM_CSROW);
    float* us    = (float*)(smem + SM_US);     // us[0..79], us[80..159]
    float* xpart = (float*)(smem + SM_XPART);
    float* hst   = (float*)(smem + SM_HST);

    const float fcb = fcb_g[0];

    // stage Whi = fp16(scale*Whh) swizzled; scale = L2E (r,z) / 2*L2E (n)
    {
        const float4* Wg = (const float4*)Whh;
        for (int v = tid; v < 384 * 32; v += NT) {
            int j = v >> 5, k4 = (v & 31) * 4;
            float sc = (j < 256) ? L2E : (2.f * L2E);
            float4 wv = Wg[v];
            uint32_t off = (uint32_t)(j * 256 + ((((k4 >> 3) ^ (j & 7))) << 4) + (k4 & 7) * 2);
            *(uint2*)(smem + SM_WHI + off) =
                make_uint2(packh2(sc * wv.x, sc * wv.y), packh2(sc * wv.z, sc * wv.w));
        }
    }
    // W rows 384..391 = fcw (fp16, UNscaled), replicated
    for (int v = tid; v < 8 * 32; v += NT) {
        int j = 384 + (v >> 5), k4 = (v & 31) * 4;
        float f0 = fcw_g[k4], f1 = fcw_g[k4 + 1], f2 = fcw_g[k4 + 2], f3 = fcw_g[k4 + 3];
        uint32_t off = (uint32_t)(j * 256 + ((((k4 >> 3) ^ (j & 7))) << 4) + (k4 & 7) * 2);
        *(uint2*)(smem + SM_WHI + off) = make_uint2(packh2(f0, f1), packh2(f2, f3));
    }
    // zero both A buffers and Hst
    for (int v = tid; v < 40960 / 8; v += NT)
        ((uint2*)(smem + SM_A0))[v] = make_uint2(0u, 0u);
    for (int v = tid; v < 80 * HSTRIDE; v += NT)
        hst[v] = 0.f;

    for (int i = tid; i < 384; i += NT) {
        float sc = (i < 256) ? L2E : (2.f * L2E);
        w0s[i] = sc * Wih[2 * i];
        w1s[i] = sc * Wih[2 * i + 1];
    }
    if (tid < 128) {
        bss[tid]       = L2E * (bih_g[tid]       + bhh_g[tid]);
        bss[128 + tid] = L2E * (bih_g[128 + tid] + bhh_g[128 + tid]);
        bss[256 + tid] = 2.f * L2E * bih_g[256 + tid];
        bss[384 + tid] = 2.f * L2E * bhh_g[256 + tid];
        fcws[tid] = fcw_g[tid];
    }
    if (tid < M_CTA) {
        int s = bid80 + tid;
        bool v = s < SEQ;
        int ss = v ? s : 0;
        int b = ss / NNN, n = ss % NNN;
        csrow[tid] = b * TT * NNN + n;
    }
    __syncthreads();

    // lane roles
    const uint32_t lx7 = lane & 7;
    const uint32_t rA  = (lane & 7) + ((lane >> 3) & 1) * 8;
    const uint32_t cA  = lane >> 4;
    const uint32_t cB  = (lane >> 3) & 1;
    const int q = lane >> 2, p4 = lane & 3;

    const uint32_t wA4 = smb + SM_WHI
        + (uint32_t)((8 * w + (lane & 7) + (((lane >> 4) & 1) << 7)) * 256);
    const uint32_t wA2 = smb + SM_WHI
        + (uint32_t)((8 * w + 256 + (lane & 7)) * 256);
    const uint32_t wA48 = smb + SM_WHI + (uint32_t)((384 + (lane & 7)) * 256);
    uint32_t rowOff[5];
#pragma unroll
    for (int mt = 0; mt < 5; mt++)
        rowOff[mt] = (uint32_t)((16 * mt + rA) * 256);

    const int c0 = 8 * w + 2 * p4;
    // mini-MMA assignment: warps 0..9, m-tile = w>>1, K-half = w&1
    const int miniMT = w >> 1;
    const int miniK0 = (w & 1) * 4;

    float w0r[2], w1r[2], br[2], w0z[2], w1z[2], bz[2],
          w0n[2], w1n[2], bi_n[2], bh_n[2], fc[2];
#pragma unroll
    for (int e = 0; e < 2; e++) {
        const int c = c0 + e;
        w0r[e] = w0s[c];       w1r[e] = w1s[c];       br[e] = bss[c];
        w0z[e] = w0s[128 + c]; w1z[e] = w1s[128 + c]; bz[e] = bss[128 + c];
        w0n[e] = w0s[256 + c]; w1n[e] = w1s[256 + c];
        bi_n[e] = bss[256 + c]; bh_n[e] = bss[384 + c];
        fc[e] = fcws[c];
    }

    for (int t = 0; t < TT; t++) {
        const uint32_t aRd = smb + ((t & 1) ? SM_A1 : SM_A0);
        const uint32_t aWrOff = (t & 1) ? SM_A0 : SM_A1;

        float acc[3][5][4];
#pragma unroll
        for (int g = 0; g < 3; g++)
#pragma unroll
            for (int mt = 0; mt < 5; mt++)
#pragma unroll
                for (int e = 0; e < 4; e++) acc[g][mt][e] = 0.f;

        // main MMA: all gates fp16 hi-only
#pragma unroll
        for (int K = 0; K < 8; K++) {
            const uint32_t offA = ((2u * K + cA) ^ lx7) << 4;
            uint32_t a[5][4];
#pragma unroll
            for (int mt = 0; mt < 5; mt++)
                LDSM4(a[mt][0], a[mt][1], a[mt][2], a[mt][3],
                      aRd + rowOff[mt] + offA);
            const uint32_t offW = ((2u * K + cB) ^ lx7) << 4;
            uint32_t bh[3][2];
            LDSM4(bh[0][0], bh[0][1], bh[1][0], bh[1][1], wA4 + offW);
            LDSM2(bh[2][0], bh[2][1], wA2 + offW);
#pragma unroll
            for (int mt = 0; mt < 5; mt++) {
                MMA16816(acc[0][mt], a[mt], bh[0]);
                MMA16816(acc[1][mt], a[mt], bh[1]);
                MMA16816(acc[2][mt], a[mt], bh[2]);
            }
        }

        // distributed mini MMA: 10 warps, K-half split (4 K-iters each)
        if (w < 10) {
            float acc48[4] = {0.f, 0.f, 0.f, 0.f};
#pragma unroll
            for (int Ki = 0; Ki < 4; Ki++) {
                const int K = miniK0 + Ki;
                const uint32_t offA = ((2u * K + cA) ^ lx7) << 4;
                const uint32_t offW = ((2u * K + cB) ^ lx7) << 4;
                uint32_t b48[2];
                LDSM2(b48[0], b48[1], wA48 + offW);
                uint32_t a[4];
                LDSM4(a[0], a[1], a[2], a[3], aRd + rowOff[miniMT] + offA);
                MMA16816(acc48, a, b48);
            }
            if (p4 == 0) {
                us[(w & 1) * 80 + 16 * miniMT + q]     = acc48[0];
                us[(w & 1) * 80 + 16 * miniMT + 8 + q] = acc48[2];
            }
        }

        // prefetch pm for this step (L2 latency hides under the barrier)
        float pvv[10];
#pragma unroll
        for (int mt = 0; mt < 5; mt++)
#pragma unroll
            for (int hf = 0; hf < 2; hf++)
                pvv[mt * 2 + hf] = __ldg(pm + csrow[16 * mt + 8 * hf + q] + t * NNN);

        __syncthreads();   // publish us[]; all A reads complete

        // ---- epilogue ----
        float* outT = out + (size_t)t * (NNN * 128);

#pragma unroll
        for (int mt = 0; mt < 5; mt++)
#pragma unroll
            for (int hf = 0; hf < 2; hf++) {
                const int row = 16 * mt + 8 * hf + q;
                const float xm = (t == 0) ? 0.f : (us[row] + us[80 + row] + fcb);
                const float pv = pvv[mt * 2 + hf];
                float2 ho2 = *(float2*)(hst + row * HSTRIDE + c0);
                const int r0i = hf * 2, r1i = hf * 2 + 1;

                const float gr0 = acc[0][mt][r0i] + fmaf(w0r[0], xm, fmaf(w1r[0], pv, br[0]));
                const float gr1 = acc[0][mt][r1i] + fmaf(w0r[1], xm, fmaf(w1r[1], pv, br[1]));
                const float gz0 = acc[1][mt][r0i] + fmaf(w0z[0], xm, fmaf(w1z[0], pv, bz[0]));
                const float gz1 = acc[1][mt][r1i] + fmaf(w0z[1], xm, fmaf(w1z[1], pv, bz[1]));
                const float dr0 = 1.f + fex2(-gr0);
                const float dr1 = 1.f + fex2(-gr1);
                const float dz0 = 1.f + fex2(-gz0);
                const float dz1 = 1.f + fex2(-gz1);
                const float m0 = dr0 * dr1, m1 = dz0 * dz1;
                const float rp = frcp(m0 * m1);
                const float r_0 = (dr1 * m1) * rp;
                const float r_1 = (dr0 * m1) * rp;
                const float z_0 = (m0 * dz1) * rp;
                const float z_1 = (m0 * dz0) * rp;

                const float a0 = fmaf(w0n[0], xm, fmaf(w1n[0], pv, bi_n[0]))
                               + r_0 * (acc[2][mt][r0i] + bh_n[0]);
                const float a1 = fmaf(w0n[1], xm, fmaf(w1n[1], pv, bi_n[1]))
                               + r_1 * (acc[2][mt][r1i] + bh_n[1]);
                const float dn0 = 1.f + fex2(a0);
                const float dn1 = 1.f + fex2(a1);
                const float rq = frcp(dn0 * dn1);
                const float nt0 = fmaf(-2.f, dn1 * rq, 1.f);
                const float nt1 = fmaf(-2.f, dn0 * rq, 1.f);

                const float hn0 = nt0 + z_0 * (ho2.x - nt0);
                const float hn1 = nt1 + z_1 * (ho2.y - nt1);

                *(float2*)(hst + row * HSTRIDE + c0) = make_float2(hn0, hn1);
                if (bid80 + row < SEQ)
                    *(float2*)(outT + (size_t)csrow[row] * 128 + c0)
                        = make_float2(hn0, hn1);
                const uint32_t aoff = (uint32_t)(row * 256 + ((w ^ q) << 4) + 4 * p4);
                *(uint32_t*)(smem + aWrOff + aoff) = packh2(hn0, hn1);

                if (t == TT - 1) {   // exact fp32 final-x partials (last step only)
                    float v = fmaf(hn0, fc[0], hn1 * fc[1]);
                    v += __shfl_xor_sync(0xFFFFFFFFu, v, 1);
                    v += __shfl_xor_sync(0xFFFFFFFFu, v, 2);
                    if (p4 == 0) xpart[w * 80 + row] = v;
                }
            }
        __syncthreads();   // A writes + (last step) xpart visible
    }

    // final xn output (exact fp32)
    if (tid < M_CTA) {
        float sx = fcb;
#pragma unroll
        for (int ww = 0; ww < 16; ww++) sx += xpart[ww * 80 + tid];
        if (bid80 + tid < SEQ)
            out[H_ELEMS + (size_t)(bid80 + tid)] = sx;
    }
}

extern "C" void kernel_launch(void* const* d_in, const int* in_sizes, int n_in,
                              void* d_out, int out_size) {
    (void)in_sizes; (void)n_in; (void)out_size;
    const float* pm  = (const float*)d_in[0];
    const float* Wih = (const float*)d_in[1];
    const float* Whh = (const float*)d_in[2];
    const float* bih = (const float*)d_in[3];
    const float* bhh = (const float*)d_in[4];
    const float* fcw = (const float*)d_in[5];
    const float* fcb = (const float*)d_in[6];
    float* out = (float*)d_out;

    cudaFuncSetAttribute(gru_mma_kernel,
                         cudaFuncAttributeMaxDynamicSharedMemorySize,
                         SMEM_BYTES);
    gru_mma_kernel<<<GRIDX, NT, SMEM_BYTES>>>(
        pm, Wih, Whh, bih, bhh, fcw, fcb, out);
}